// round 1
// baseline (speedup 1.0000x reference)
#include <cuda_runtime.h>
#include <math.h>

// Problem constants
#define N 4096
#define D 512
#define NB 151            // num histogram bins
#define HALFB 75          // (NUM_STEPS-1)/2
#define INV_STEP 75.0f    // 1/STEP, STEP = 2/150

// Tiling
#define BM 128
#define BN 128
#define BK 32
#define NT (N / BM)       // 32 tiles per dim
#define NTILES (NT * (NT + 1) / 2)   // 528 upper-tri tiles

// Scratch (static device memory -- no allocations)
__device__ float g_fn[(size_t)N * D];   // normalized features
__device__ float g_hist[2 * NB];        // [0..150] pos, [151..301] neg (unnormalized)

// ---------------------------------------------------------------------------
// Kernel 0: zero the global histograms
// ---------------------------------------------------------------------------
__global__ void zero_hist_kernel() {
    int t = threadIdx.x;
    if (t < 2 * NB) g_hist[t] = 0.0f;
}

// ---------------------------------------------------------------------------
// Kernel 1: L2-normalize each row of features into g_fn
// ---------------------------------------------------------------------------
__global__ void norm_kernel(const float* __restrict__ f) {
    int row = blockIdx.x;
    const float* src = f + (size_t)row * D;
    float ss = 0.0f;
    for (int k = threadIdx.x; k < D; k += 128) {
        float v = src[k];
        ss += v * v;
    }
    // warp reduce
    #pragma unroll
    for (int o = 16; o > 0; o >>= 1) ss += __shfl_down_sync(0xffffffffu, ss, o);
    __shared__ float wsum[4];
    if ((threadIdx.x & 31) == 0) wsum[threadIdx.x >> 5] = ss;
    __syncthreads();
    float tot = wsum[0] + wsum[1] + wsum[2] + wsum[3];
    float inv = 1.0f / sqrtf(tot);
    for (int k = threadIdx.x; k < D; k += 128) {
        g_fn[(size_t)row * D + k] = src[k] * inv;
    }
}

// ---------------------------------------------------------------------------
// Kernel 2: tiled f @ f^T over upper-triangular tiles, fused soft histogram
// ---------------------------------------------------------------------------
__global__ void __launch_bounds__(256) pair_hist_kernel(const int* __restrict__ classes) {
    __shared__ float As[BK][BM + 4];
    __shared__ float Bs[BK][BN + 4];
    __shared__ float wh[8][2 * 152];   // per-warp replicated histograms (152 = padded 151)
    __shared__ int clsA[BM];
    __shared__ int clsB[BN];

    int tid = threadIdx.x;

    // Decode linear tile id -> (br, bc) with br <= bc
    int t = blockIdx.x;
    int br = 0;
    while (t >= NT - br) { t -= NT - br; br++; }
    int bc = br + t;
    int rowBase = br * BM;
    int colBase = bc * BN;

    // init per-warp hists + class tiles
    for (int b = tid; b < 8 * 2 * 152; b += 256) ((float*)wh)[b] = 0.0f;
    if (tid < BM) clsA[tid] = classes[rowBase + tid];
    else          clsB[tid - BM] = classes[colBase + (tid - BM)];

    float acc[8][8];
    #pragma unroll
    for (int u = 0; u < 8; u++)
        #pragma unroll
        for (int v = 0; v < 8; v++) acc[u][v] = 0.0f;

    int lr = tid >> 3;          // 0..31 (load row)
    int lc = (tid & 7) * 4;     // 0,4,...,28 (load k-col base)
    int ty = tid >> 4;          // 0..15
    int tx = tid & 15;          // 0..15

    for (int kt = 0; kt < D; kt += BK) {
        __syncthreads();
        #pragma unroll
        for (int it = 0; it < 4; it++) {
            int r = lr + it * 32;
            float4 a = *(const float4*)&g_fn[(size_t)(rowBase + r) * D + kt + lc];
            As[lc + 0][r] = a.x; As[lc + 1][r] = a.y;
            As[lc + 2][r] = a.z; As[lc + 3][r] = a.w;
            float4 b = *(const float4*)&g_fn[(size_t)(colBase + r) * D + kt + lc];
            Bs[lc + 0][r] = b.x; Bs[lc + 1][r] = b.y;
            Bs[lc + 2][r] = b.z; Bs[lc + 3][r] = b.w;
        }
        __syncthreads();
        #pragma unroll
        for (int k = 0; k < BK; k++) {
            float4 a0 = *(const float4*)&As[k][ty * 8];
            float4 a1 = *(const float4*)&As[k][ty * 8 + 4];
            float4 b0 = *(const float4*)&Bs[k][tx * 8];
            float4 b1 = *(const float4*)&Bs[k][tx * 8 + 4];
            float av[8] = {a0.x, a0.y, a0.z, a0.w, a1.x, a1.y, a1.z, a1.w};
            float bv[8] = {b0.x, b0.y, b0.z, b0.w, b1.x, b1.y, b1.z, b1.w};
            #pragma unroll
            for (int u = 0; u < 8; u++)
                #pragma unroll
                for (int v = 0; v < 8; v++)
                    acc[u][v] = fmaf(av[u], bv[v], acc[u][v]);
        }
    }

    // Epilogue: soft-bin each (i,j) with i<j into per-warp shared histograms
    float* hw = wh[tid >> 5];
    #pragma unroll
    for (int u = 0; u < 8; u++) {
        int i  = rowBase + ty * 8 + u;
        int ci = clsA[ty * 8 + u];
        #pragma unroll
        for (int v = 0; v < 8; v++) {
            int j = colBase + tx * 8 + v;
            if (i < j) {
                int hsel = (ci == clsB[tx * 8 + v]) ? 0 : 1;   // 0 = pos, 1 = neg
                float x  = acc[u][v] * INV_STEP;
                float kf = floorf(x);
                float fr = x - kf;
                int   kI = (int)kf + HALFB;
                int lo = min(max(kI, 0), NB - 1);
                int hi = min(max(kI + 1, 0), NB - 1);
                float* h = hw + hsel * 152;
                atomicAdd(h + lo, 1.0f - fr);
                atomicAdd(h + hi, fr);
            }
        }
    }
    __syncthreads();

    // Reduce the 8 warp copies and flush to global
    for (int b = tid; b < 2 * NB; b += 256) {
        int hsel = b / NB;
        int idx  = b - hsel * NB;
        float s = 0.0f;
        #pragma unroll
        for (int w = 0; w < 8; w++) s += wh[w][hsel * 152 + idx];
        atomicAdd(&g_hist[b], s);
    }
}

// ---------------------------------------------------------------------------
// Kernel 3: finalize -- normalize hists, cumsum pos, dot with neg
// ---------------------------------------------------------------------------
__global__ void finalize_kernel(float* __restrict__ out) {
    if (threadIdx.x != 0 || blockIdx.x != 0) return;
    float sp = 0.0f, sn = 0.0f;
    for (int i = 0; i < NB; i++) { sp += g_hist[i]; sn += g_hist[NB + i]; }
    float invp = 1.0f / sp, invn = 1.0f / sn;
    float c = 0.0f, loss = 0.0f;
    for (int i = 0; i < NB; i++) {
        c += g_hist[i] * invp;
        loss += (g_hist[NB + i] * invn) * c;
    }
    out[0] = loss;
}

// ---------------------------------------------------------------------------
extern "C" void kernel_launch(void* const* d_in, const int* in_sizes, int n_in,
                              void* d_out, int out_size) {
    const float* features = (const float*)d_in[0];
    const int*   classes  = (const int*)d_in[1];
    float*       out      = (float*)d_out;

    zero_hist_kernel<<<1, 320>>>();
    norm_kernel<<<N, 128>>>(features);
    pair_hist_kernel<<<NTILES, 256>>>(classes);
    finalize_kernel<<<1, 32>>>(out);
}

// round 3
// speedup vs baseline: 1.7184x; 1.7184x over previous
#include <cuda_runtime.h>
#include <cuda_bf16.h>
#include <cstdint>
#include <math.h>

// ---------------------------------------------------------------------------
// Problem constants
// ---------------------------------------------------------------------------
#define N 4096
#define D 512
#define NB 151
#define HALFB 75
#define INV_STEP 75.0f

#define BM 128
#define BK 64             // bf16 K per chunk = 128B rows (SW128 swizzle atom)
#define NCHUNK (D / BK)   // 8
#define NT (N / BM)       // 32
#define NTILES (NT * (NT + 1) / 2)  // 528
#define STAGES 2
#define STAGE_BYTES 65536           // 4 tiles (Ahi,Alo,Bhi,Blo) x 128 x 128B

// dynamic smem layout
#define OFF_CLS   0                 // 256 ints = 1024B  (clsA[128], clsB[128])
#define OFF_HIST  1024              // 8 warps * 2 par * 2 hsel * 152 f32 = 19456B
#define OFF_TILES 20480
#define SMEM_TOTAL (OFF_TILES + STAGES * STAGE_BYTES)   // 151552

// ---------------------------------------------------------------------------
// Inline PTX helpers (all baseline sm_80-class instructions)
// ---------------------------------------------------------------------------
__device__ __forceinline__ uint32_t smem_u32(const void* p) {
    uint32_t a;
    asm("{ .reg .u64 t; cvta.to.shared.u64 t, %1; cvt.u32.u64 %0, t; }" : "=r"(a) : "l"(p));
    return a;
}
__device__ __forceinline__ void cp16(uint32_t dst, const void* src) {
    asm volatile("cp.async.cg.shared.global [%0], [%1], 16;" :: "r"(dst), "l"(src) : "memory");
}
__device__ __forceinline__ void cp_commit() {
    asm volatile("cp.async.commit_group;" ::: "memory");
}
__device__ __forceinline__ void cp_wait0() {
    asm volatile("cp.async.wait_group 0;" ::: "memory");
}
__device__ __forceinline__ void ldmx4(uint32_t* r, uint32_t addr) {
    asm volatile("ldmatrix.sync.aligned.m8n8.x4.shared.b16 {%0,%1,%2,%3}, [%4];"
                 : "=r"(r[0]), "=r"(r[1]), "=r"(r[2]), "=r"(r[3]) : "r"(addr));
}
__device__ __forceinline__ void mma16816(float* c, const uint32_t* a, const uint32_t* b) {
    asm volatile("mma.sync.aligned.m16n8k16.row.col.f32.bf16.bf16.f32 "
                 "{%0,%1,%2,%3}, {%4,%5,%6,%7}, {%8,%9}, {%0,%1,%2,%3};"
                 : "+f"(c[0]), "+f"(c[1]), "+f"(c[2]), "+f"(c[3])
                 : "r"(a[0]), "r"(a[1]), "r"(a[2]), "r"(a[3]), "r"(b[0]), "r"(b[1]));
}

// ---------------------------------------------------------------------------
// Scratch (static device memory -- no allocations)
// ---------------------------------------------------------------------------
__device__ __nv_bfloat16 g_hi[(size_t)N * D];
__device__ __nv_bfloat16 g_lo[(size_t)N * D];
__device__ float g_hist[2 * NB];

// ---------------------------------------------------------------------------
// Kernel 0: zero global histograms
// ---------------------------------------------------------------------------
__global__ void zero_hist_kernel() {
    int t = threadIdx.x;
    if (t < 2 * NB) g_hist[t] = 0.0f;
}

// ---------------------------------------------------------------------------
// Kernel 1: L2-normalize each row, split into hi/lo bf16
// ---------------------------------------------------------------------------
__global__ void norm_split_kernel(const float* __restrict__ f) {
    int row = blockIdx.x;
    const float* src = f + (size_t)row * D;
    float ss = 0.0f;
    for (int k = threadIdx.x; k < D; k += 128) {
        float v = src[k];
        ss += v * v;
    }
    #pragma unroll
    for (int o = 16; o > 0; o >>= 1) ss += __shfl_down_sync(0xffffffffu, ss, o);
    __shared__ float wsum[4];
    if ((threadIdx.x & 31) == 0) wsum[threadIdx.x >> 5] = ss;
    __syncthreads();
    float inv = 1.0f / sqrtf(wsum[0] + wsum[1] + wsum[2] + wsum[3]);
    for (int k = threadIdx.x; k < D; k += 128) {
        float v = src[k] * inv;
        __nv_bfloat16 hi = __float2bfloat16(v);
        float rem = v - __bfloat162float(hi);
        g_hi[(size_t)row * D + k] = hi;
        g_lo[(size_t)row * D + k] = __float2bfloat16(rem);
    }
}

// ---------------------------------------------------------------------------
// Kernel 2: HMMA split-bf16 f@f^T over upper-tri tiles + fused histogram
// 256 threads = 8 warps, warp grid 2(m) x 4(n), warp tile 64x32
// ---------------------------------------------------------------------------
__global__ void __launch_bounds__(256) pair_mma_hist_kernel(const int* __restrict__ classes) {
    extern __shared__ char smem[];
    uint32_t sb = smem_u32(smem);
    int tid = threadIdx.x;
    int wid = tid >> 5;
    int lane = tid & 31;

    // decode tile id -> (br, bc), br <= bc
    int t = blockIdx.x;
    int br = 0;
    while (t >= NT - br) { t -= NT - br; br++; }
    int bc = br + t;
    int rowBase = br * BM;
    int colBase = bc * BM;

    // class tiles + per-warp histograms
    int* clsS = (int*)(smem + OFF_CLS);
    if (tid < 128) clsS[tid] = classes[rowBase + tid];
    else           clsS[tid] = classes[colBase + tid - 128];
    float* histS = (float*)(smem + OFF_HIST);
    for (int b = tid; b < 8 * 2 * 2 * 152; b += 256) histS[b] = 0.0f;

    // gmem byte-base pointers per tile: 0=Ahi 1=Alo 2=Bhi 3=Blo
    const char* gsrc[4];
    gsrc[0] = (const char*)(g_hi + (size_t)rowBase * D);
    gsrc[1] = (const char*)(g_lo + (size_t)rowBase * D);
    gsrc[2] = (const char*)(g_hi + (size_t)colBase * D);
    gsrc[3] = (const char*)(g_lo + (size_t)colBase * D);

    uint32_t tilesBase = sb + OFF_TILES;
    int ldr = (tid >> 3);      // load row-within-32
    int ldp = tid & 7;         // 16B piece within 128B row

    // issue chunk-0 loads
    {
        #pragma unroll
        for (int it = 0; it < 16; it++) {
            const int tile = it >> 2;
            int r = ((it & 3) << 5) + ldr;
            uint32_t dst = tilesBase + tile * 16384 + r * 128 + ((ldp ^ (r & 7)) << 4);
            const char* src = gsrc[tile] + ((size_t)r * D + ldp * 8) * 2;
            cp16(dst, src);
        }
        cp_commit();
    }

    float acc[4][4][4];
    #pragma unroll
    for (int mi = 0; mi < 4; mi++)
        #pragma unroll
        for (int ni = 0; ni < 4; ni++)
            #pragma unroll
            for (int q = 0; q < 4; q++) acc[mi][ni][q] = 0.0f;

    int wm = wid & 1;          // 0..1
    int wn = wid >> 1;         // 0..3
    int blk = lane >> 3;       // ldmatrix 8x8 block id
    int lrow = lane & 7;

    for (int c = 0; c < NCHUNK; c++) {
        cp_wait0();
        __syncthreads();
        // prefetch next chunk into the other stage (overlaps with compute)
        if (c + 1 < NCHUNK) {
            uint32_t stb = tilesBase + ((c + 1) & 1) * STAGE_BYTES;
            #pragma unroll
            for (int it = 0; it < 16; it++) {
                const int tile = it >> 2;
                int r = ((it & 3) << 5) + ldr;
                uint32_t dst = stb + tile * 16384 + r * 128 + ((ldp ^ (r & 7)) << 4);
                const char* src = gsrc[tile] + ((size_t)r * D + (size_t)(c + 1) * BK + ldp * 8) * 2;
                cp16(dst, src);
            }
        }
        cp_commit();

        uint32_t aHi = tilesBase + (c & 1) * STAGE_BYTES;
        uint32_t bHi = aHi + 32768;

        #pragma unroll
        for (int ks = 0; ks < 4; ks++) {
            uint32_t a_hi[4][4], a_lo[4][4], b_hi[4][2], b_lo[4][2];
            // A frags: 4 x m16k16
            #pragma unroll
            for (int mi = 0; mi < 4; mi++) {
                int row = wm * 64 + mi * 16 + ((blk & 1) << 3) + lrow;
                int piece = ks * 2 + (blk >> 1);
                uint32_t ad = aHi + row * 128 + ((piece ^ (row & 7)) << 4);
                ldmx4(a_hi[mi], ad);
                ldmx4(a_lo[mi], ad + 16384);
            }
            // B frags: 2 x (n16k16 -> two n8k16 frags)
            #pragma unroll
            for (int ni2 = 0; ni2 < 2; ni2++) {
                int row = wn * 32 + ni2 * 16 + ((blk >> 1) << 3) + lrow;
                int piece = ks * 2 + (blk & 1);
                uint32_t bd = bHi + row * 128 + ((piece ^ (row & 7)) << 4);
                uint32_t r4[4];
                ldmx4(r4, bd);
                b_hi[ni2 * 2][0] = r4[0]; b_hi[ni2 * 2][1] = r4[1];
                b_hi[ni2 * 2 + 1][0] = r4[2]; b_hi[ni2 * 2 + 1][1] = r4[3];
                ldmx4(r4, bd + 16384);
                b_lo[ni2 * 2][0] = r4[0]; b_lo[ni2 * 2][1] = r4[1];
                b_lo[ni2 * 2 + 1][0] = r4[2]; b_lo[ni2 * 2 + 1][1] = r4[3];
            }
            // 3-term split product
            #pragma unroll
            for (int mi = 0; mi < 4; mi++)
                #pragma unroll
                for (int ni = 0; ni < 4; ni++) {
                    mma16816(acc[mi][ni], a_hi[mi], b_hi[ni]);
                    mma16816(acc[mi][ni], a_hi[mi], b_lo[ni]);
                    mma16816(acc[mi][ni], a_lo[mi], b_hi[ni]);
                }
        }
        __syncthreads();
    }

    // ---- fused epilogue: bin directly from accumulator registers ----
    int par = lane & 1;
    float* hw = histS + ((wid * 2 + par) * 2) * 152;
    int iBase = rowBase + wm * 64 + (lane >> 2);
    int jBase = colBase + wn * 32 + (lane & 3) * 2;
    const int* clsB = clsS + 128;

    #pragma unroll
    for (int mi = 0; mi < 4; mi++) {
        int i0 = iBase + mi * 16;
        int ci0 = clsS[i0 - rowBase];
        int ci1 = clsS[i0 + 8 - rowBase];
        #pragma unroll
        for (int ni = 0; ni < 4; ni++) {
            int j0 = jBase + ni * 8;
            int cj0 = clsB[j0 - colBase];
            int cj1 = clsB[j0 + 1 - colBase];
            #pragma unroll
            for (int q = 0; q < 4; q++) {
                int i = i0 + ((q >> 1) << 3);
                int j = j0 + (q & 1);
                if (i < j) {
                    int ci = (q & 2) ? ci1 : ci0;
                    int cj = (q & 1) ? cj1 : cj0;
                    float x = acc[mi][ni][q] * INV_STEP;
                    float kf = floorf(x);
                    float fr = x - kf;
                    int kI = (int)kf + HALFB;
                    int lo = min(max(kI, 0), NB - 1);
                    int hi = min(max(kI + 1, 0), NB - 1);
                    float* h = hw + ((ci == cj) ? 0 : 152);
                    atomicAdd(h + lo, 1.0f - fr);
                    atomicAdd(h + hi, fr);
                }
            }
        }
    }
    __syncthreads();

    // reduce the 16 copies, flush to global
    for (int b = tid; b < 2 * NB; b += 256) {
        int hsel = b / NB;
        int idx = b - hsel * NB;
        float s = 0.0f;
        #pragma unroll
        for (int cpy = 0; cpy < 16; cpy++)
            s += histS[(cpy * 2 + hsel) * 152 + idx];
        atomicAdd(&g_hist[b], s);
    }
}

// ---------------------------------------------------------------------------
// Kernel 3: finalize -- parallel scan + dot
// ---------------------------------------------------------------------------
__global__ void finalize_kernel(float* __restrict__ out) {
    __shared__ float sp[NB];
    __shared__ float sn[NB];
    __shared__ float acc2[2];
    int t = threadIdx.x;  // 256
    if (t < NB) { sp[t] = g_hist[t]; sn[t] = g_hist[NB + t]; }
    if (t == 0) { acc2[0] = 0.0f; acc2[1] = 0.0f; }
    __syncthreads();
    for (int off = 1; off < NB; off <<= 1) {
        float v = 0.0f;
        if (t < NB && t >= off) v = sp[t - off];
        __syncthreads();
        if (t < NB && t >= off) sp[t] += v;
        __syncthreads();
    }
    if (t < NB) {
        atomicAdd(&acc2[0], sn[t]);
        atomicAdd(&acc2[1], sn[t] * sp[t]);
    }
    __syncthreads();
    if (t == 0) out[0] = acc2[1] / (sp[NB - 1] * acc2[0]);
}

// ---------------------------------------------------------------------------
extern "C" void kernel_launch(void* const* d_in, const int* in_sizes, int n_in,
                              void* d_out, int out_size) {
    const float* features = (const float*)d_in[0];
    const int*   classes  = (const int*)d_in[1];
    float*       out      = (float*)d_out;

    cudaFuncSetAttribute(pair_mma_hist_kernel,
                         cudaFuncAttributeMaxDynamicSharedMemorySize, SMEM_TOTAL);

    zero_hist_kernel<<<1, 320>>>();
    norm_split_kernel<<<N, 128>>>(features);
    pair_mma_hist_kernel<<<NTILES, 256, SMEM_TOTAL>>>(classes);
    finalize_kernel<<<1, 256>>>(out);
}

// round 4
// speedup vs baseline: 3.3165x; 1.9300x over previous
#include <cuda_runtime.h>
#include <cuda_bf16.h>
#include <cstdint>
#include <math.h>

// ---------------------------------------------------------------------------
// Problem constants
// ---------------------------------------------------------------------------
#define N 4096
#define D 512
#define NB 151
#define HALFB 75
#define INV_STEP 75.0f

#define BM 128
#define BK 64             // bf16 K per chunk = 128B rows (swizzle atom)
#define NCHUNK (D / BK)   // 8
#define NT (N / BM)       // 32
#define NTILES (NT * (NT + 1) / 2)  // 528
#define STAGES 2
#define STAGE_BYTES 32768           // 2 tiles (A,B) x 128 rows x 128B

// dynamic smem layout
#define OFF_CLS   0                 // 256 ints = 1024B
#define OFF_HIST  1024              // 16 copies * 2 hsel * 152 f32 = 19456B
#define OFF_TILES 20480
#define SMEM_TOTAL (OFF_TILES + STAGES * STAGE_BYTES)   // 86016

// ---------------------------------------------------------------------------
// Inline PTX helpers (baseline sm_80-class instructions only)
// ---------------------------------------------------------------------------
__device__ __forceinline__ uint32_t smem_u32(const void* p) {
    uint32_t a;
    asm("{ .reg .u64 t; cvta.to.shared.u64 t, %1; cvt.u32.u64 %0, t; }" : "=r"(a) : "l"(p));
    return a;
}
__device__ __forceinline__ void cp16(uint32_t dst, const void* src) {
    asm volatile("cp.async.cg.shared.global [%0], [%1], 16;" :: "r"(dst), "l"(src) : "memory");
}
__device__ __forceinline__ void cp_commit() {
    asm volatile("cp.async.commit_group;" ::: "memory");
}
__device__ __forceinline__ void cp_wait0() {
    asm volatile("cp.async.wait_group 0;" ::: "memory");
}
__device__ __forceinline__ void ldmx4(uint32_t* r, uint32_t addr) {
    asm volatile("ldmatrix.sync.aligned.m8n8.x4.shared.b16 {%0,%1,%2,%3}, [%4];"
                 : "=r"(r[0]), "=r"(r[1]), "=r"(r[2]), "=r"(r[3]) : "r"(addr));
}
__device__ __forceinline__ void mma16816(float* c, const uint32_t* a, const uint32_t* b) {
    asm volatile("mma.sync.aligned.m16n8k16.row.col.f32.bf16.bf16.f32 "
                 "{%0,%1,%2,%3}, {%4,%5,%6,%7}, {%8,%9}, {%0,%1,%2,%3};"
                 : "+f"(c[0]), "+f"(c[1]), "+f"(c[2]), "+f"(c[3])
                 : "r"(a[0]), "r"(a[1]), "r"(a[2]), "r"(a[3]), "r"(b[0]), "r"(b[1]));
}

// ---------------------------------------------------------------------------
// Scratch (static device memory -- no allocations)
// ---------------------------------------------------------------------------
__device__ __nv_bfloat16 g_bf[(size_t)N * D];
__device__ float g_hist[2 * NB];

// ---------------------------------------------------------------------------
// Kernel 0: zero global histograms
// ---------------------------------------------------------------------------
__global__ void zero_hist_kernel() {
    int t = threadIdx.x;
    if (t < 2 * NB) g_hist[t] = 0.0f;
}

// ---------------------------------------------------------------------------
// Kernel 1: L2-normalize each row into bf16
// ---------------------------------------------------------------------------
__global__ void norm_kernel(const float* __restrict__ f) {
    int row = blockIdx.x;
    const float* src = f + (size_t)row * D;
    float ss = 0.0f;
    for (int k = threadIdx.x; k < D; k += 128) {
        float v = src[k];
        ss += v * v;
    }
    #pragma unroll
    for (int o = 16; o > 0; o >>= 1) ss += __shfl_down_sync(0xffffffffu, ss, o);
    __shared__ float wsum[4];
    if ((threadIdx.x & 31) == 0) wsum[threadIdx.x >> 5] = ss;
    __syncthreads();
    float inv = 1.0f / sqrtf(wsum[0] + wsum[1] + wsum[2] + wsum[3]);
    for (int k = threadIdx.x; k < D; k += 128) {
        g_bf[(size_t)row * D + k] = __float2bfloat16(src[k] * inv);
    }
}

// ---------------------------------------------------------------------------
// Kernel 2: HMMA bf16 f@f^T over upper-tri tiles + fused histogram
// 256 threads = 8 warps, warp grid 2(m) x 4(n), warp tile 64x32
// ---------------------------------------------------------------------------
__global__ void __launch_bounds__(256) pair_mma_hist_kernel(const int* __restrict__ classes) {
    extern __shared__ char smem[];
    uint32_t sb = smem_u32(smem);
    int tid = threadIdx.x;
    int wid = tid >> 5;
    int lane = tid & 31;

    // decode tile id -> (br, bc), br <= bc
    int t = blockIdx.x;
    int br = 0;
    while (t >= NT - br) { t -= NT - br; br++; }
    int bc = br + t;
    int rowBase = br * BM;
    int colBase = bc * BM;

    int* clsS = (int*)(smem + OFF_CLS);
    if (tid < 128) clsS[tid] = classes[rowBase + tid];
    else           clsS[tid] = classes[colBase + tid - 128];
    float* histS = (float*)(smem + OFF_HIST);
    for (int b = tid; b < 16 * 2 * 152; b += 256) histS[b] = 0.0f;

    const char* gA = (const char*)(g_bf + (size_t)rowBase * D);
    const char* gB = (const char*)(g_bf + (size_t)colBase * D);

    uint32_t tilesBase = sb + OFF_TILES;
    int ldr = tid >> 3;        // 0..31 row-within-32
    int ldp = tid & 7;         // 16B piece within 128B row

    // issue chunk-0 loads: A tile then B tile, each 128 rows x 128B
    {
        #pragma unroll
        for (int it = 0; it < 8; it++) {
            const int tile = it >> 2;              // 0=A, 1=B
            int r = ((it & 3) << 5) + ldr;
            uint32_t dst = tilesBase + tile * 16384 + r * 128 + ((ldp ^ (r & 7)) << 4);
            const char* src = (tile ? gB : gA) + ((size_t)r * D + ldp * 8) * 2;
            cp16(dst, src);
        }
        cp_commit();
    }

    float acc[4][4][4];
    #pragma unroll
    for (int mi = 0; mi < 4; mi++)
        #pragma unroll
        for (int ni = 0; ni < 4; ni++)
            #pragma unroll
            for (int q = 0; q < 4; q++) acc[mi][ni][q] = 0.0f;

    int wm = wid & 1;          // 0..1
    int wn = wid >> 1;         // 0..3
    int blk = lane >> 3;       // ldmatrix 8x8 block id
    int lrow = lane & 7;

    for (int c = 0; c < NCHUNK; c++) {
        cp_wait0();
        __syncthreads();
        if (c + 1 < NCHUNK) {
            uint32_t stb = tilesBase + ((c + 1) & 1) * STAGE_BYTES;
            #pragma unroll
            for (int it = 0; it < 8; it++) {
                const int tile = it >> 2;
                int r = ((it & 3) << 5) + ldr;
                uint32_t dst = stb + tile * 16384 + r * 128 + ((ldp ^ (r & 7)) << 4);
                const char* src = (tile ? gB : gA) +
                                  ((size_t)r * D + (size_t)(c + 1) * BK + ldp * 8) * 2;
                cp16(dst, src);
            }
        }
        cp_commit();

        uint32_t aBase = tilesBase + (c & 1) * STAGE_BYTES;
        uint32_t bBase = aBase + 16384;

        #pragma unroll
        for (int ks = 0; ks < 4; ks++) {
            uint32_t af[4][4], bf[4][2];
            #pragma unroll
            for (int mi = 0; mi < 4; mi++) {
                int row = wm * 64 + mi * 16 + ((blk & 1) << 3) + lrow;
                int piece = ks * 2 + (blk >> 1);
                ldmx4(af[mi], aBase + row * 128 + ((piece ^ (row & 7)) << 4));
            }
            #pragma unroll
            for (int ni2 = 0; ni2 < 2; ni2++) {
                int row = wn * 32 + ni2 * 16 + ((blk >> 1) << 3) + lrow;
                int piece = ks * 2 + (blk & 1);
                uint32_t r4[4];
                ldmx4(r4, bBase + row * 128 + ((piece ^ (row & 7)) << 4));
                bf[ni2 * 2][0] = r4[0]; bf[ni2 * 2][1] = r4[1];
                bf[ni2 * 2 + 1][0] = r4[2]; bf[ni2 * 2 + 1][1] = r4[3];
            }
            #pragma unroll
            for (int mi = 0; mi < 4; mi++)
                #pragma unroll
                for (int ni = 0; ni < 4; ni++)
                    mma16816(acc[mi][ni], af[mi], bf[ni]);
        }
        __syncthreads();
    }

    // ---- fused epilogue: bin directly from accumulator registers ----
    int par = lane & 1;
    float* hw = histS + ((wid * 2 + par) * 2) * 152;
    int iBase = rowBase + wm * 64 + (lane >> 2);
    int jBase = colBase + wn * 32 + (lane & 3) * 2;
    const int* clsB = clsS + 128;

    #pragma unroll
    for (int mi = 0; mi < 4; mi++) {
        int i0 = iBase + mi * 16;
        int ci0 = clsS[i0 - rowBase];
        int ci1 = clsS[i0 + 8 - rowBase];
        #pragma unroll
        for (int ni = 0; ni < 4; ni++) {
            int j0 = jBase + ni * 8;
            int cj0 = clsB[j0 - colBase];
            int cj1 = clsB[j0 + 1 - colBase];
            #pragma unroll
            for (int q = 0; q < 4; q++) {
                int i = i0 + ((q >> 1) << 3);
                int j = j0 + (q & 1);
                if (i < j) {
                    int ci = (q & 2) ? ci1 : ci0;
                    int cj = (q & 1) ? cj1 : cj0;
                    float x = acc[mi][ni][q] * INV_STEP;
                    float kf = floorf(x);
                    float fr = x - kf;
                    int kI = (int)kf + HALFB;
                    int lo = min(max(kI, 0), NB - 1);
                    int hi = min(max(kI + 1, 0), NB - 1);
                    float* h = hw + ((ci == cj) ? 0 : 152);
                    atomicAdd(h + lo, 1.0f - fr);
                    atomicAdd(h + hi, fr);
                }
            }
        }
    }
    __syncthreads();

    // reduce the 16 copies, flush to global
    for (int b = tid; b < 2 * NB; b += 256) {
        int hsel = b / NB;
        int idx = b - hsel * NB;
        float s = 0.0f;
        #pragma unroll
        for (int cpy = 0; cpy < 16; cpy++)
            s += histS[(cpy * 2 + hsel) * 152 + idx];
        atomicAdd(&g_hist[b], s);
    }
}

// ---------------------------------------------------------------------------
// Kernel 3: finalize -- parallel scan + dot
// ---------------------------------------------------------------------------
__global__ void finalize_kernel(float* __restrict__ out) {
    __shared__ float sp[NB];
    __shared__ float sn[NB];
    __shared__ float acc2[2];
    int t = threadIdx.x;  // 256
    if (t < NB) { sp[t] = g_hist[t]; sn[t] = g_hist[NB + t]; }
    if (t == 0) { acc2[0] = 0.0f; acc2[1] = 0.0f; }
    __syncthreads();
    for (int off = 1; off < NB; off <<= 1) {
        float v = 0.0f;
        if (t < NB && t >= off) v = sp[t - off];
        __syncthreads();
        if (t < NB && t >= off) sp[t] += v;
        __syncthreads();
    }
    if (t < NB) {
        atomicAdd(&acc2[0], sn[t]);
        atomicAdd(&acc2[1], sn[t] * sp[t]);
    }
    __syncthreads();
    if (t == 0) out[0] = acc2[1] / (sp[NB - 1] * acc2[0]);
}

// ---------------------------------------------------------------------------
extern "C" void kernel_launch(void* const* d_in, const int* in_sizes, int n_in,
                              void* d_out, int out_size) {
    const float* features = (const float*)d_in[0];
    const int*   classes  = (const int*)d_in[1];
    float*       out      = (float*)d_out;

    cudaFuncSetAttribute(pair_mma_hist_kernel,
                         cudaFuncAttributeMaxDynamicSharedMemorySize, SMEM_TOTAL);

    zero_hist_kernel<<<1, 320>>>();
    norm_kernel<<<N, 128>>>(features);
    pair_mma_hist_kernel<<<NTILES, 256, SMEM_TOTAL>>>(classes);
    finalize_kernel<<<1, 256>>>(out);
}